// round 5
// baseline (speedup 1.0000x reference)
#include <cuda_runtime.h>

// out = relu( GroupNorm32( Wv @ feat + bv, gn_v_g, gn_v_b ) )
// (softmax-weighted sum in the reference is identity: v is constant along the
//  softmax axis and softmax rows sum to 1).
//
// feat [2,128,512], Wv [128,128], out [2,128,512].
// Grid: 128 blocks = B(2) x group(32) x slice(2), 256 threads.
// Thread layout: tx = 64 float4 columns, ty = 4 cc-quarters (32 cc each).
// Thread: 32 cc x 4 points x 4 channels = 512 FMA-inst, 32 LDG.128.
// cc-partials combined via deterministic smem tree; cross-slice GN stats via
// device-global partials + parity-flag handshake (each replay adds exactly 2
// arrivals/group; spin until even; 128 blocks <= 148 SMs so both partners are
// co-resident -> no deadlock; no reset needed across graph replays).

#define C_CH     128
#define NPT      512
#define CH_PER_G 4
#define EPS_GN   1e-5f
#define NTHREADS 256
#define SLICES   2
#define CC_SPLIT 4
#define CC_PER_T (C_CH / CC_SPLIT)   // 32
#define CHUNK    8
#define ROW4     (NPT / 4)           // 128 float4 per feat row

__device__ float    g_part[2][32][SLICES][2];  // [b][g][slice][{sum,sumsq}]
__device__ unsigned g_flag[2][32];             // zero-init at module load

__device__ __forceinline__ float4 f4add(float4 a, float4 b) {
    a.x += b.x; a.y += b.y; a.z += b.z; a.w += b.w; return a;
}

__global__ __launch_bounds__(NTHREADS, 1)
void fused_v_gn_relu_kernel(const float* __restrict__ feat,
                            const float* __restrict__ Wv,
                            const float* __restrict__ bv,
                            const float* __restrict__ gamma,
                            const float* __restrict__ beta,
                            float* __restrict__ out) {
    const int x  = blockIdx.x;
    const int s  = x & 1;            // slice 0..1
    const int g  = (x >> 1) & 31;    // group 0..31
    const int b  = x >> 6;           // batch 0..1
    const int c0 = g * CH_PER_G;
    const int t  = threadIdx.x;      // 0..255
    const int tx = t & 63;           // float4 column within slice
    const int ty = t >> 6;           // cc quarter

    __shared__ float  wt_s[C_CH * CH_PER_G];            // transposed Wv, 2KB
    __shared__ float4 part_s[CC_SPLIT * CH_PER_G * 64]; // [ty][c][tx], 16KB
    __shared__ float  red_s[2 * (NTHREADS / 32)];
    __shared__ float  stat_s[2];

    // Stage Wv transposed: wt_s[cc*4 + c] = Wv[(c0+c)*128 + cc].
    if (t < C_CH) {
        const int cc = t;
        #pragma unroll
        for (int c = 0; c < CH_PER_G; c++)
            wt_s[cc * CH_PER_G + c] = Wv[(c0 + c) * C_CH + cc];
    }
    __syncthreads();

    // feat as float4 rows; this thread's column, offset to its cc quarter.
    const float4* fp = (const float4*)(feat + (size_t)b * C_CH * NPT)
                       + (size_t)(ty * CC_PER_T) * ROW4 + s * 64 + tx;
    const float4* wt4 = (const float4*)wt_s;
    const int wbase = ty * CC_PER_T;

    float4 acc[CH_PER_G];
    #pragma unroll
    for (int c = 0; c < CH_PER_G; c++) {
        const float bvc = (ty == 0) ? bv[c0 + c] : 0.f;
        acc[c].x = bvc; acc[c].y = bvc; acc[c].z = bvc; acc[c].w = bvc;
    }

    // Double-buffered mainloop over this thread's 32 cc, chunks of 8.
    float4 cur[CHUNK], nxt[CHUNK];
    #pragma unroll
    for (int i = 0; i < CHUNK; i++) cur[i] = fp[i * ROW4];

    #pragma unroll
    for (int cb = 0; cb < CC_PER_T; cb += CHUNK) {
        if (cb + CHUNK < CC_PER_T) {
            #pragma unroll
            for (int i = 0; i < CHUNK; i++)
                nxt[i] = fp[(cb + CHUNK + i) * ROW4];
        }
        #pragma unroll
        for (int i = 0; i < CHUNK; i++) {
            const float4 w = wt4[wbase + cb + i];   // broadcast LDS.128
            const float4 f = cur[i];
            acc[0].x = fmaf(w.x, f.x, acc[0].x);
            acc[0].y = fmaf(w.x, f.y, acc[0].y);
            acc[0].z = fmaf(w.x, f.z, acc[0].z);
            acc[0].w = fmaf(w.x, f.w, acc[0].w);
            acc[1].x = fmaf(w.y, f.x, acc[1].x);
            acc[1].y = fmaf(w.y, f.y, acc[1].y);
            acc[1].z = fmaf(w.y, f.z, acc[1].z);
            acc[1].w = fmaf(w.y, f.w, acc[1].w);
            acc[2].x = fmaf(w.z, f.x, acc[2].x);
            acc[2].y = fmaf(w.z, f.y, acc[2].y);
            acc[2].z = fmaf(w.z, f.z, acc[2].z);
            acc[2].w = fmaf(w.z, f.w, acc[2].w);
            acc[3].x = fmaf(w.w, f.x, acc[3].x);
            acc[3].y = fmaf(w.w, f.y, acc[3].y);
            acc[3].z = fmaf(w.w, f.z, acc[3].z);
            acc[3].w = fmaf(w.w, f.w, acc[3].w);
        }
        #pragma unroll
        for (int i = 0; i < CHUNK; i++) cur[i] = nxt[i];
    }

    // Publish cc-partials: part_s[ty][c][tx].
    #pragma unroll
    for (int c = 0; c < CH_PER_G; c++)
        part_s[(ty * CH_PER_G + c) * 64 + tx] = acc[c];
    __syncthreads();

    // Deterministic tree reduction over ty: buffers of 256 float4 each.
    // Step 1: buf0 += buf2, buf1 += buf3 (256 threads, one float4 per buffer).
    part_s[t]       = f4add(part_s[t],       part_s[t + 512]);
    part_s[t + 256] = f4add(part_s[t + 256], part_s[t + 768]);
    __syncthreads();
    // Step 2: buf0 += buf1.
    part_s[t] = f4add(part_s[t], part_s[t + 256]);
    __syncthreads();

    // GN stats over this slice's 1024 final v values (part_s[0..256)).
    {
        const float4 v = part_s[t];
        float ps  = v.x + v.y + v.z + v.w;
        float pss = fmaf(v.x, v.x, fmaf(v.y, v.y, fmaf(v.z, v.z, v.w * v.w)));
        #pragma unroll
        for (int off = 16; off > 0; off >>= 1) {
            ps  += __shfl_xor_sync(0xffffffffu, ps,  off);
            pss += __shfl_xor_sync(0xffffffffu, pss, off);
        }
        const int lane = t & 31, wid = t >> 5;
        if (lane == 0) {
            red_s[wid] = ps;
            red_s[(NTHREADS / 32) + wid] = pss;
        }
    }
    __syncthreads();

    if (t == 0) {
        float ts = 0.f, tss = 0.f;
        #pragma unroll
        for (int w = 0; w < NTHREADS / 32; w++) {
            ts  += red_s[w];
            tss += red_s[(NTHREADS / 32) + w];
        }
        g_part[b][g][s][0] = ts;
        g_part[b][g][s][1] = tss;
        __threadfence();
        atomicAdd(&g_flag[b][g], 1u);

        volatile unsigned* fl = &g_flag[b][g];
        while ((*fl) & 1u) { }
        __threadfence();

        const float tot_s  = g_part[b][g][0][0] + g_part[b][g][1][0];
        const float tot_ss = g_part[b][g][0][1] + g_part[b][g][1][1];
        const float inv_n  = 1.0f / (float)(CH_PER_G * NPT);
        const float m      = tot_s * inv_n;
        const float var    = tot_ss * inv_n - m * m;   // biased (jnp.var)
        stat_s[0] = m;
        stat_s[1] = rsqrtf(var + EPS_GN);
    }
    __syncthreads();

    const float m   = stat_s[0];
    const float rst = stat_s[1];

    // Store: thread t owns channel c = t>>6, float4 column pt4 = t&63.
    {
        const int c   = t >> 6;
        const int pt4 = t & 63;
        const float ga = gamma[c0 + c] * rst;
        const float be = beta[c0 + c];
        const float4 v = part_s[t];
        float4 y;
        y.x = fmaxf(fmaf(v.x - m, ga, be), 0.f);
        y.y = fmaxf(fmaf(v.y - m, ga, be), 0.f);
        y.z = fmaxf(fmaf(v.z - m, ga, be), 0.f);
        y.w = fmaxf(fmaf(v.w - m, ga, be), 0.f);
        float4* ob = (float4*)(out + (size_t)b * C_CH * NPT);
        ob[(size_t)(c0 + c) * ROW4 + s * 64 + pt4] = y;
    }
}

extern "C" void kernel_launch(void* const* d_in, const int* in_sizes, int n_in,
                              void* d_out, int out_size) {
    // metadata order:
    // 0 feat, 1 Wk, 2 bk, 3 Wq, 4 bq, 5 Wv, 6 bv, 7 gn_v_g, 8 gn_v_b,
    // 9 gn1_g, 10 gn1_b, 11 W1, 12 b1, 13 gn2_g, 14 gn2_b, 15 W2, 16 b2
    const float* feat = (const float*)d_in[0];
    const float* Wv   = (const float*)d_in[5];
    const float* bv   = (const float*)d_in[6];
    const float* gn_g = (const float*)d_in[7];
    const float* gn_b = (const float*)d_in[8];
    float* out = (float*)d_out;

    (void)in_sizes; (void)n_in; (void)out_size;

    fused_v_gn_relu_kernel<<<2 * 32 * SLICES, NTHREADS>>>(feat, Wv, bv,
                                                          gn_g, gn_b, out);
}

// round 7
// speedup vs baseline: 1.2727x; 1.2727x over previous
#include <cuda_runtime.h>
#include <cstdint>

// out = relu( GroupNorm32( Wv @ feat + bv, gn_v_g, gn_v_b ) )
// (softmax-weighted sum in the reference is identity: v is constant along the
//  softmax axis and softmax rows sum to 1).
//
// feat [2,128,512], Wv [128,128], out [2,128,512].
// Grid: 128 blocks = 64 clusters of 2 (cluster = the two point-slices of one
// GroupNorm group).  128 threads/block, 4 warps.
// Thread: tx = 64 float4 columns, ty = 2 cc-halves; 64 cc x 4 pts x 4 ch =
// 64 LDG.128 + 1024 FMA-inst, double-buffered in chunks of 8.
// cc-halves combined with ONE smem step; cross-slice GN stats exchanged via
// mapa + st.shared::cluster + barrier.cluster (no global atomics, no spin,
// graph-replay safe, deterministic combine order slice0+slice1).

#define C_CH     128
#define NPT      512
#define CH_PER_G 4
#define EPS_GN   1e-5f
#define NTHREADS 128
#define ROW4     (NPT / 4)     // 128 float4 per feat row
#define CHUNK    8
#define CC_HALF  (C_CH / 2)    // 64 cc per ty

__device__ __forceinline__ uint32_t smem_u32(const void* p) {
    uint32_t a;
    asm("{ .reg .u64 t; cvta.to.shared.u64 t, %1; cvt.u32.u64 %0, t; }"
        : "=r"(a) : "l"(p));
    return a;
}

__device__ __forceinline__ float4 f4add(float4 a, float4 b) {
    a.x += b.x; a.y += b.y; a.z += b.z; a.w += b.w; return a;
}

__global__ __launch_bounds__(NTHREADS, 1) __cluster_dims__(2, 1, 1)
void fused_v_gn_relu_kernel(const float* __restrict__ feat,
                            const float* __restrict__ Wv,
                            const float* __restrict__ bv,
                            const float* __restrict__ gamma,
                            const float* __restrict__ beta,
                            float* __restrict__ out) {
    const int x    = blockIdx.x;
    const int s    = x & 1;          // slice (== cluster rank)
    const int pair = x >> 1;
    const int g    = pair & 31;      // group 0..31
    const int b    = pair >> 5;      // batch 0..1
    const int c0   = g * CH_PER_G;
    const int t    = threadIdx.x;    // 0..127
    const int tx   = t & 63;         // float4 column within slice
    const int ty   = t >> 6;         // cc half

    __shared__ float  wt_s[C_CH * CH_PER_G];        // transposed Wv, 2KB
    __shared__ float4 part_s[2 * CH_PER_G * 64];    // [ty][c][col], 8KB
    __shared__ float  red_s[2 * (NTHREADS / 32)];
    __shared__ float  xch[2][2];                    // [slice][{sum,sumsq}]

    // Stage Wv transposed: wt_s[cc*4 + c] = Wv[(c0+c)*128 + cc].
    {
        const int cc = t;
        #pragma unroll
        for (int c = 0; c < CH_PER_G; c++)
            wt_s[cc * CH_PER_G + c] = Wv[(c0 + c) * C_CH + cc];
    }
    __syncthreads();

    const float4* fp = (const float4*)(feat + (size_t)b * C_CH * NPT)
                       + (size_t)(ty * CC_HALF) * ROW4 + s * 64 + tx;
    const float4* wt4 = (const float4*)wt_s;
    const int wbase = ty * CC_HALF;

    float4 acc[CH_PER_G];
    #pragma unroll
    for (int c = 0; c < CH_PER_G; c++) {
        const float bvc = (ty == 0) ? bv[c0 + c] : 0.f;
        acc[c].x = bvc; acc[c].y = bvc; acc[c].z = bvc; acc[c].w = bvc;
    }

    // Double-buffered mainloop: 8 chunks x (8 LDG.128 + 128 FMA-inst).
    float4 cur[CHUNK], nxt[CHUNK];
    #pragma unroll
    for (int i = 0; i < CHUNK; i++) cur[i] = fp[i * ROW4];

    #pragma unroll
    for (int cb = 0; cb < CC_HALF; cb += CHUNK) {
        if (cb + CHUNK < CC_HALF) {
            #pragma unroll
            for (int i = 0; i < CHUNK; i++)
                nxt[i] = fp[(cb + CHUNK + i) * ROW4];
        }
        #pragma unroll
        for (int i = 0; i < CHUNK; i++) {
            const float4 w = wt4[wbase + cb + i];   // broadcast LDS.128
            const float4 f = cur[i];
            acc[0].x = fmaf(w.x, f.x, acc[0].x);
            acc[0].y = fmaf(w.x, f.y, acc[0].y);
            acc[0].z = fmaf(w.x, f.z, acc[0].z);
            acc[0].w = fmaf(w.x, f.w, acc[0].w);
            acc[1].x = fmaf(w.y, f.x, acc[1].x);
            acc[1].y = fmaf(w.y, f.y, acc[1].y);
            acc[1].z = fmaf(w.y, f.z, acc[1].z);
            acc[1].w = fmaf(w.y, f.w, acc[1].w);
            acc[2].x = fmaf(w.z, f.x, acc[2].x);
            acc[2].y = fmaf(w.z, f.y, acc[2].y);
            acc[2].z = fmaf(w.z, f.z, acc[2].z);
            acc[2].w = fmaf(w.z, f.w, acc[2].w);
            acc[3].x = fmaf(w.w, f.x, acc[3].x);
            acc[3].y = fmaf(w.w, f.y, acc[3].y);
            acc[3].z = fmaf(w.w, f.z, acc[3].z);
            acc[3].w = fmaf(w.w, f.w, acc[3].w);
        }
        #pragma unroll
        for (int i = 0; i < CHUNK; i++) cur[i] = nxt[i];
    }

    // Publish cc-half partials and combine (single smem step).
    #pragma unroll
    for (int c = 0; c < CH_PER_G; c++)
        part_s[ty * 256 + c * 64 + tx] = acc[c];
    __syncthreads();

    // Thread t owns flattened [c][col] indices t and t+128.
    const float4 v0 = f4add(part_s[t],       part_s[256 + t]);
    const float4 v1 = f4add(part_s[t + 128], part_s[256 + t + 128]);

    // Slice-local GN partial over this thread's 8 values.
    {
        float ps  = v0.x + v0.y + v0.z + v0.w + v1.x + v1.y + v1.z + v1.w;
        float pss = fmaf(v0.x, v0.x, fmaf(v0.y, v0.y,
                    fmaf(v0.z, v0.z, fmaf(v0.w, v0.w,
                    fmaf(v1.x, v1.x, fmaf(v1.y, v1.y,
                    fmaf(v1.z, v1.z, v1.w * v1.w)))))));
        #pragma unroll
        for (int off = 16; off > 0; off >>= 1) {
            ps  += __shfl_xor_sync(0xffffffffu, ps,  off);
            pss += __shfl_xor_sync(0xffffffffu, pss, off);
        }
        const int lane = t & 31, wid = t >> 5;
        if (lane == 0) {
            red_s[wid] = ps;
            red_s[(NTHREADS / 32) + wid] = pss;
        }
    }
    __syncthreads();

    if (t == 0) {
        float ts = 0.f, tss = 0.f;
        #pragma unroll
        for (int w = 0; w < NTHREADS / 32; w++) {
            ts  += red_s[w];
            tss += red_s[(NTHREADS / 32) + w];
        }
        // Write own partial locally and into the peer CTA's smem.
        xch[s][0] = ts;
        xch[s][1] = tss;
        const uint32_t local = smem_u32(&xch[s][0]);
        uint32_t remote;
        asm("mapa.shared::cluster.u32 %0, %1, %2;"
            : "=r"(remote) : "r"(local), "r"(s ^ 1));
        asm volatile("st.shared::cluster.f32 [%0], %1;"
                     :: "r"(remote), "f"(ts) : "memory");
        asm volatile("st.shared::cluster.f32 [%0+4], %1;"
                     :: "r"(remote), "f"(tss) : "memory");
    }

    // Cluster barrier: orders the remote stores, makes both partials visible.
    asm volatile("barrier.cluster.arrive.aligned;" ::: "memory");
    asm volatile("barrier.cluster.wait.aligned;"   ::: "memory");

    // Every thread computes stats redundantly (fixed order: slice0 + slice1).
    const float tot_s  = xch[0][0] + xch[1][0];
    const float tot_ss = xch[0][1] + xch[1][1];
    const float inv_n  = 1.0f / (float)(CH_PER_G * NPT);
    const float m      = tot_s * inv_n;
    const float var    = tot_ss * inv_n - m * m;   // biased (jnp.var)
    const float rst    = rsqrtf(var + EPS_GN);

    // Store: thread t owns (c, col) = (t>>6, t&63) and (2+(t>>6), t&63).
    {
        float4* ob = (float4*)(out + (size_t)b * C_CH * NPT);
        const int col = t & 63;
        const int ca  = t >> 6;
        const int cb2 = 2 + ca;

        const float ga0 = gamma[c0 + ca] * rst,  be0 = beta[c0 + ca];
        const float ga1 = gamma[c0 + cb2] * rst, be1 = beta[c0 + cb2];

        float4 y;
        y.x = fmaxf(fmaf(v0.x - m, ga0, be0), 0.f);
        y.y = fmaxf(fmaf(v0.y - m, ga0, be0), 0.f);
        y.z = fmaxf(fmaf(v0.z - m, ga0, be0), 0.f);
        y.w = fmaxf(fmaf(v0.w - m, ga0, be0), 0.f);
        ob[(size_t)(c0 + ca) * ROW4 + s * 64 + col] = y;

        y.x = fmaxf(fmaf(v1.x - m, ga1, be1), 0.f);
        y.y = fmaxf(fmaf(v1.y - m, ga1, be1), 0.f);
        y.z = fmaxf(fmaf(v1.z - m, ga1, be1), 0.f);
        y.w = fmaxf(fmaf(v1.w - m, ga1, be1), 0.f);
        ob[(size_t)(c0 + cb2) * ROW4 + s * 64 + col] = y;
    }
}

extern "C" void kernel_launch(void* const* d_in, const int* in_sizes, int n_in,
                              void* d_out, int out_size) {
    // metadata order:
    // 0 feat, 1 Wk, 2 bk, 3 Wq, 4 bq, 5 Wv, 6 bv, 7 gn_v_g, 8 gn_v_b,
    // 9 gn1_g, 10 gn1_b, 11 W1, 12 b1, 13 gn2_g, 14 gn2_b, 15 W2, 16 b2
    const float* feat = (const float*)d_in[0];
    const float* Wv   = (const float*)d_in[5];
    const float* bv   = (const float*)d_in[6];
    const float* gn_g = (const float*)d_in[7];
    const float* gn_b = (const float*)d_in[8];
    float* out = (float*)d_out;

    (void)in_sizes; (void)n_in; (void)out_size;

    fused_v_gn_relu_kernel<<<128, NTHREADS>>>(feat, Wv, bv, gn_g, gn_b, out);
}